// round 1
// baseline (speedup 1.0000x reference)
#include <cuda_runtime.h>
#include <cuda_bf16.h>
#include <float.h>

// Dequantized int4 weights, [4][2048] row-major (output-major).
__device__ float g_Wq[4 * 2048];

// ---------------------------------------------------------------------------
// Kernel 1: per-tensor symmetric int4 quantize-dequantize of W [4,2048].
// scale = max|W| / 7 ; Wq = clip(rint(W/scale), -8, 7) * scale
// Single block, 256 threads.
// ---------------------------------------------------------------------------
__global__ void quantize_w_kernel(const float* __restrict__ W) {
    __shared__ float s_warp[8];
    __shared__ float s_scale;
    const int t = threadIdx.x;

    float m = 0.0f;
    #pragma unroll
    for (int k = 0; k < 32; k++) {
        m = fmaxf(m, fabsf(W[t + k * 256]));
    }
    // warp max
    #pragma unroll
    for (int off = 16; off > 0; off >>= 1)
        m = fmaxf(m, __shfl_xor_sync(0xFFFFFFFFu, m, off));
    if ((t & 31) == 0) s_warp[t >> 5] = m;
    __syncthreads();
    if (t == 0) {
        float mm = s_warp[0];
        #pragma unroll
        for (int w = 1; w < 8; w++) mm = fmaxf(mm, s_warp[w]);
        s_scale = mm / 7.0f;
    }
    __syncthreads();
    const float scale = s_scale;
    const float inv_scale = 1.0f / scale;

    #pragma unroll
    for (int k = 0; k < 32; k++) {
        const int i = t + k * 256;
        float q = rintf(W[i] * inv_scale);   // rint = half-to-even, matches jnp.round
        q = fminf(fmaxf(q, -8.0f), 7.0f);
        g_Wq[i] = q * scale;
    }
}

// ---------------------------------------------------------------------------
// Kernel 2: fused MaxPool3d(2) + linear(2048->4, Wq) + bias + softmax.
// One block (256 threads) per batch row. Each thread handles 8 pooled
// features; each pooled feature is the max of a 2x2x2 input block
// (4 coalesced float2 loads).
//
// x layout: [B, C=4, D=16, H=16, W=16] f32, 16384 floats per batch row.
// pooled feature index f in [0,2048): c = f>>9, pd=(f>>6)&7, ph=(f>>3)&7, pw=f&7
// input offset = c*4096 + (2*pd)*256 + (2*ph)*16 + 2*pw
// ---------------------------------------------------------------------------
__global__ void __launch_bounds__(256)
fused_pool_linear_softmax_kernel(const float* __restrict__ x,
                                 const float* __restrict__ bias,
                                 float* __restrict__ out) {
    __shared__ float s_red[8][4];

    const int b = blockIdx.x;
    const int t = threadIdx.x;
    const float* __restrict__ xb = x + (size_t)b * 16384;

    float acc0 = 0.0f, acc1 = 0.0f, acc2 = 0.0f, acc3 = 0.0f;

    #pragma unroll
    for (int k = 0; k < 8; k++) {
        const int f   = t + k * 256;
        const int c   = f >> 9;
        const int rem = f & 511;
        const int pd  = rem >> 6;
        const int ph  = (rem >> 3) & 7;
        const int pw  = rem & 7;

        const float* p = xb + c * 4096 + pd * 512 + ph * 32 + pw * 2;
        const float2 a0 = *reinterpret_cast<const float2*>(p);
        const float2 a1 = *reinterpret_cast<const float2*>(p + 16);
        const float2 a2 = *reinterpret_cast<const float2*>(p + 256);
        const float2 a3 = *reinterpret_cast<const float2*>(p + 272);

        const float m = fmaxf(fmaxf(fmaxf(a0.x, a0.y), fmaxf(a1.x, a1.y)),
                              fmaxf(fmaxf(a2.x, a2.y), fmaxf(a3.x, a3.y)));

        acc0 = fmaf(m, g_Wq[f],        acc0);
        acc1 = fmaf(m, g_Wq[2048 + f], acc1);
        acc2 = fmaf(m, g_Wq[4096 + f], acc2);
        acc3 = fmaf(m, g_Wq[6144 + f], acc3);
    }

    // warp reduce 4 accumulators
    #pragma unroll
    for (int off = 16; off > 0; off >>= 1) {
        acc0 += __shfl_xor_sync(0xFFFFFFFFu, acc0, off);
        acc1 += __shfl_xor_sync(0xFFFFFFFFu, acc1, off);
        acc2 += __shfl_xor_sync(0xFFFFFFFFu, acc2, off);
        acc3 += __shfl_xor_sync(0xFFFFFFFFu, acc3, off);
    }
    const int wid = t >> 5;
    if ((t & 31) == 0) {
        s_red[wid][0] = acc0;
        s_red[wid][1] = acc1;
        s_red[wid][2] = acc2;
        s_red[wid][3] = acc3;
    }
    __syncthreads();

    if (t == 0) {
        float l0 = bias[0], l1 = bias[1], l2 = bias[2], l3 = bias[3];
        #pragma unroll
        for (int w = 0; w < 8; w++) {
            l0 += s_red[w][0];
            l1 += s_red[w][1];
            l2 += s_red[w][2];
            l3 += s_red[w][3];
        }
        const float mx = fmaxf(fmaxf(l0, l1), fmaxf(l2, l3));
        const float e0 = __expf(l0 - mx);
        const float e1 = __expf(l1 - mx);
        const float e2 = __expf(l2 - mx);
        const float e3 = __expf(l3 - mx);
        const float inv = 1.0f / (e0 + e1 + e2 + e3);
        float4 r = make_float4(e0 * inv, e1 * inv, e2 * inv, e3 * inv);
        *reinterpret_cast<float4*>(out + (size_t)b * 4) = r;
    }
}

extern "C" void kernel_launch(void* const* d_in, const int* in_sizes, int n_in,
                              void* d_out, int out_size) {
    const float* x = (const float*)d_in[0];   // [8192,4,16,16,16]
    const float* W = (const float*)d_in[1];   // [4,2048]
    const float* b = (const float*)d_in[2];   // [4]
    float* out = (float*)d_out;               // [8192,4]

    quantize_w_kernel<<<1, 256>>>(W);
    fused_pool_linear_softmax_kernel<<<8192, 256>>>(x, b, out);
}

// round 2
// speedup vs baseline: 1.0373x; 1.0373x over previous
#include <cuda_runtime.h>
#include <cuda_bf16.h>
#include <float.h>

// Dequantized int4 weights, [4][2048] row-major (output-major).
__device__ float g_Wq[4 * 2048];

// ---------------------------------------------------------------------------
// Kernel 1: per-tensor symmetric int4 quantize-dequantize of W [4,2048].
// scale = max|W| / 7 ; Wq = clip(rint(W/scale), -8, 7) * scale
// Single block, 1024 threads.
// ---------------------------------------------------------------------------
__global__ void __launch_bounds__(1024)
quantize_w_kernel(const float* __restrict__ W) {
    __shared__ float s_warp[32];
    __shared__ float s_scale;
    const int t = threadIdx.x;

    float m = 0.0f;
    #pragma unroll
    for (int k = 0; k < 8; k++)
        m = fmaxf(m, fabsf(W[t + k * 1024]));

    #pragma unroll
    for (int off = 16; off > 0; off >>= 1)
        m = fmaxf(m, __shfl_xor_sync(0xFFFFFFFFu, m, off));
    if ((t & 31) == 0) s_warp[t >> 5] = m;
    __syncthreads();
    if (t == 0) {
        float mm = s_warp[0];
        #pragma unroll
        for (int w = 1; w < 32; w++) mm = fmaxf(mm, s_warp[w]);
        s_scale = mm / 7.0f;
    }
    __syncthreads();
    const float scale = s_scale;
    const float inv_scale = 1.0f / scale;

    #pragma unroll
    for (int k = 0; k < 8; k++) {
        const int i = t + k * 1024;
        float q = rintf(W[i] * inv_scale);   // half-to-even, matches jnp.round
        q = fminf(fmaxf(q, -8.0f), 7.0f);
        g_Wq[i] = q * scale;
    }
}

// ---------------------------------------------------------------------------
// Kernel 2: fused MaxPool3d(2) + linear(2048->4, Wq) + bias + softmax.
// One block (256 threads) per batch row. Each thread handles 4 feature-PAIRS
// (8 pooled features). Each pair comes from 4 coalesced float4 loads
// (LDG.128), covering two adjacent 2x2x2 pooling windows along W.
//
// x layout: [B, C=4, D=16, H=16, W=16] f32, 16384 floats per row.
// pair index fp in [0,1024): c = fp>>8, rem = fp&255,
//   pd = rem>>5, ph = (rem>>2)&7, pwp = rem&3
// base float offset = c*4096 + pd*512 + ph*32 + pwp*4
// loads: base(+0), +16 (h+1), +256 (d+1), +272 (d+1,h+1)
// features: f0 = 2*fp (from .x/.y), f1 = 2*fp+1 (from .z/.w)
// ---------------------------------------------------------------------------
__global__ void __launch_bounds__(256)
fused_pool_linear_softmax_kernel(const float* __restrict__ x,
                                 const float* __restrict__ bias,
                                 float* __restrict__ out) {
    __shared__ float s_red[8][4];

    const int b = blockIdx.x;
    const int t = threadIdx.x;
    const float* __restrict__ xb = x + (size_t)b * 16384;

    float acc0 = 0.0f, acc1 = 0.0f, acc2 = 0.0f, acc3 = 0.0f;

    #pragma unroll
    for (int k = 0; k < 4; k++) {
        const int fp  = t + k * 256;
        const int c   = fp >> 8;
        const int rem = fp & 255;
        const int pd  = rem >> 5;
        const int ph  = (rem >> 2) & 7;
        const int pwp = rem & 3;

        const float4* p = reinterpret_cast<const float4*>(
            xb + c * 4096 + pd * 512 + ph * 32 + pwp * 4);

        const float4 a0 = __ldcs(p);        // (d0, h0)
        const float4 a1 = __ldcs(p + 4);    // (d0, h1)
        const float4 a2 = __ldcs(p + 64);   // (d1, h0)
        const float4 a3 = __ldcs(p + 68);   // (d1, h1)

        const float m0 = fmaxf(fmaxf(fmaxf(a0.x, a0.y), fmaxf(a1.x, a1.y)),
                               fmaxf(fmaxf(a2.x, a2.y), fmaxf(a3.x, a3.y)));
        const float m1 = fmaxf(fmaxf(fmaxf(a0.z, a0.w), fmaxf(a1.z, a1.w)),
                               fmaxf(fmaxf(a2.z, a2.w), fmaxf(a3.z, a3.w)));

        const int f2 = fp * 2;
        const float2 w0 = *reinterpret_cast<const float2*>(&g_Wq[f2]);
        const float2 w1 = *reinterpret_cast<const float2*>(&g_Wq[2048 + f2]);
        const float2 w2 = *reinterpret_cast<const float2*>(&g_Wq[4096 + f2]);
        const float2 w3 = *reinterpret_cast<const float2*>(&g_Wq[6144 + f2]);

        acc0 = fmaf(m0, w0.x, fmaf(m1, w0.y, acc0));
        acc1 = fmaf(m0, w1.x, fmaf(m1, w1.y, acc1));
        acc2 = fmaf(m0, w2.x, fmaf(m1, w2.y, acc2));
        acc3 = fmaf(m0, w3.x, fmaf(m1, w3.y, acc3));
    }

    // warp reduce 4 accumulators
    #pragma unroll
    for (int off = 16; off > 0; off >>= 1) {
        acc0 += __shfl_xor_sync(0xFFFFFFFFu, acc0, off);
        acc1 += __shfl_xor_sync(0xFFFFFFFFu, acc1, off);
        acc2 += __shfl_xor_sync(0xFFFFFFFFu, acc2, off);
        acc3 += __shfl_xor_sync(0xFFFFFFFFu, acc3, off);
    }
    const int wid = t >> 5;
    if ((t & 31) == 0) {
        s_red[wid][0] = acc0;
        s_red[wid][1] = acc1;
        s_red[wid][2] = acc2;
        s_red[wid][3] = acc3;
    }
    __syncthreads();

    if (t == 0) {
        float l0 = bias[0], l1 = bias[1], l2 = bias[2], l3 = bias[3];
        #pragma unroll
        for (int w = 0; w < 8; w++) {
            l0 += s_red[w][0];
            l1 += s_red[w][1];
            l2 += s_red[w][2];
            l3 += s_red[w][3];
        }
        const float mx = fmaxf(fmaxf(l0, l1), fmaxf(l2, l3));
        const float e0 = __expf(l0 - mx);
        const float e1 = __expf(l1 - mx);
        const float e2 = __expf(l2 - mx);
        const float e3 = __expf(l3 - mx);
        const float inv = 1.0f / (e0 + e1 + e2 + e3);
        float4 r = make_float4(e0 * inv, e1 * inv, e2 * inv, e3 * inv);
        *reinterpret_cast<float4*>(out + (size_t)b * 4) = r;
    }
}

extern "C" void kernel_launch(void* const* d_in, const int* in_sizes, int n_in,
                              void* d_out, int out_size) {
    const float* x = (const float*)d_in[0];   // [8192,4,16,16,16]
    const float* W = (const float*)d_in[1];   // [4,2048]
    const float* b = (const float*)d_in[2];   // [4]
    float* out = (float*)d_out;               // [8192,4]

    quantize_w_kernel<<<1, 1024>>>(W);
    fused_pool_linear_softmax_kernel<<<8192, 256>>>(x, b, out);
}